// round 5
// baseline (speedup 1.0000x reference)
#include <cuda_runtime.h>
#include <cstdint>

#define BB 16
#define T_STEPS 20
#define NT 2241
#define GRID_CONV 592

// ---------------- persistent device state ----------------
__device__ float g_v [BB*3*32*32];
__device__ float g_s [BB*3*32*32];
__device__ float g_m1[BB*64*32*32];
__device__ float g_o1[BB*64*32*32];
__device__ float g_o1p[BB*64*16*16];
__device__ float g_m2[BB*128*16*16];
__device__ float g_o2[BB*128*16*16];
__device__ float g_m3[BB*128*16*16];
__device__ float g_o3[BB*128*16*16];
__device__ float g_f [BB*8192];
__device__ float g_m4[BB*1024];
__device__ float g_o4[BB*1024];
__device__ float g_m5[BB*1024];
__device__ float g_o5[BB*1024];
__device__ float g_mo[BB*10];
__device__ int   g_tick;

// ---------------- partial-sum slabs (deterministic K-split) ----------------
__device__ float g_c1s[BB*64*32*32];        // conv1 raw out
__device__ float g_s2 [4][BB*128*16*16];    // conv2: 4 cin-splits
__device__ float g_s3 [8][BB*128*16*16];    // conv3: 8 cin-splits
__device__ float g_s4 [32][BB*1024];        // fc1: 32 k-splits
__device__ float g_s5 [4][BB*1024];         // fc2: 4 k-splits

// ---------------- f32x2 helpers ----------------
__device__ __forceinline__ uint64_t pk2(float lo, float hi) {
    uint64_t r; asm("mov.b64 %0, {%1, %2};" : "=l"(r) : "f"(lo), "f"(hi)); return r;
}
__device__ __forceinline__ void upk(uint64_t v, float& lo, float& hi) {
    asm("mov.b64 {%0, %1}, %2;" : "=f"(lo), "=f"(hi) : "l"(v));
}
__device__ __forceinline__ void fma2(uint64_t& d, uint64_t a, uint64_t b) {
    asm("fma.rn.f32x2 %0, %1, %2, %0;" : "+l"(d) : "l"(a), "l"(b));
}

// ---------------- zero state ----------------
__global__ void zero_state() {
    int n  = gridDim.x * blockDim.x;
    int i0 = blockIdx.x * blockDim.x + threadIdx.x;
    for (int i = i0; i < BB*3*32*32;   i += n) { g_v[i] = 0.f; g_s[i] = 0.f; }
    for (int i = i0; i < BB*64*32*32;  i += n) { g_m1[i] = 0.f; g_o1[i] = 0.f; g_c1s[i] = 0.f; }
    for (int i = i0; i < BB*128*16*16; i += n) {
        g_m2[i] = 0.f; g_o2[i] = 0.f; g_m3[i] = 0.f; g_o3[i] = 0.f;
        #pragma unroll
        for (int k = 0; k < 4; k++) g_s2[k][i] = 0.f;
        #pragma unroll
        for (int k = 0; k < 8; k++) g_s3[k][i] = 0.f;
    }
    for (int i = i0; i < BB*1024; i += n) {
        g_m4[i] = 0.f; g_o4[i] = 0.f; g_m5[i] = 0.f; g_o5[i] = 0.f;
        #pragma unroll
        for (int k = 0; k < 32; k++) g_s4[k][i] = 0.f;
        #pragma unroll
        for (int k = 0; k < 4;  k++) g_s5[k][i] = 0.f;
    }
    for (int i = i0; i < BB*10; i += n) g_mo[i] = 0.f;
}

// keeps ncu -s 5 aligned onto a conv_step launch
__global__ void nop_k() {}

// ---------------- per-step spike kernel: membrane completion + thresholds ----------------
__global__ void __launch_bounds__(256) spike_step(const float* __restrict__ x) {
    int i = blockIdx.x * 256 + threadIdx.x;
    if (i == 0) g_tick = 0;
    if (i < 49152) {
        float v = g_v[i] + x[i];
        v = v - g_s[i];
        g_v[i] = v;
        g_s[i] = (v > 1.0f) ? 1.0f : 0.0f;
    } else if (i < 311296) {
        int p  = i - 49152;                  // (B*64, 16, 16) pooled
        int px = p & 15, py = (p >> 4) & 15, bc = p >> 8;
        int base = (bc*32 + py*2)*32 + px*2;
        float sum = 0.f;
        #pragma unroll
        for (int dy = 0; dy < 2; dy++)
            #pragma unroll
            for (int dx = 0; dx < 2; dx++) {
                int idx = base + dy*32 + dx;
                float m = (g_m1[idx] + g_c1s[idx]) - g_o1[idx];
                float o = (m > 1.0f) ? 1.0f : 0.0f;
                g_m1[idx] = m;
                g_o1[idx] = o;
                sum += o;
            }
        g_o1p[p] = sum * 0.25f;
    } else if (i < 835584) {
        int p = i - 311296;
        float inp = ((g_s2[0][p] + g_s2[1][p]) + g_s2[2][p]) + g_s2[3][p];
        float m = (g_m2[p] + inp) - g_o2[p];
        g_m2[p] = m;
        g_o2[p] = (m > 1.0f) ? 1.0f : 0.0f;
    } else if (i < 966656) {
        int p  = i - 835584;                 // (B*128, 8, 8) pooled
        int px = p & 7, py = (p >> 3) & 7, bc = p >> 6;
        int base = (bc*16 + py*2)*16 + px*2;
        float sum = 0.f;
        #pragma unroll
        for (int dy = 0; dy < 2; dy++)
            #pragma unroll
            for (int dx = 0; dx < 2; dx++) {
                int idx = base + dy*16 + dx;
                float inp = 0.f;
                #pragma unroll
                for (int k = 0; k < 8; k++) inp += g_s3[k][idx];
                float m = (g_m3[idx] + inp) - g_o3[idx];
                float o = (m > 1.0f) ? 1.0f : 0.0f;
                g_m3[idx] = m;
                g_o3[idx] = o;
                sum += o;
            }
        int b = bc >> 7, c = bc & 127;
        g_f[b*8192 + c*64 + py*8 + px] = sum * 0.25f;
    } else if (i < 983040) {
        int p = i - 966656;
        float inp = 0.f;
        #pragma unroll 8
        for (int k = 0; k < 32; k++) inp += g_s4[k][p];
        float m = (g_m4[p] + inp) - g_o4[p];
        g_m4[p] = m;
        g_o4[p] = (m > 1.0f) ? 1.0f : 0.0f;
    } else if (i < 999424) {
        int p = i - 983040;
        float inp = ((g_s5[0][p] + g_s5[1][p]) + g_s5[2][p]) + g_s5[3][p];
        float m = (g_m5[p] + inp) - g_o5[p];
        g_m5[p] = m;
        g_o5[p] = (m > 1.0f) ? 1.0f : 0.0f;
    }
}

// ---------------- conv tile: 16 oc x full 16x16 image x 16 cin ----------------
// 128 threads = 4 warps; warp = one 4-oc group (weight LDS warp-uniform);
// lane = row*2 + xh; thread tile = 4 oc x 1 row x 8 px (f32x2 pairs).
// Input smem skew +2 floats when ((r>>1)&1): 8B-unit index = 10r+((r>>1)&1)+4xh+j,
// S={0,10,5,15,8,2,13,7} per half-warp, S and S+4 disjoint -> conflict-free.
#define IN_PITCH 368
__device__ __forceinline__ void conv_tile(
    const float* __restrict__ in, const float* __restrict__ W,
    float* __restrict__ slab, int CIN, int cb, int b, int oc0, float* sm)
{
    float* in_s = sm;                 // 16 * 368 = 5888 floats
    float* w_s  = sm + 5888;          // 16c*3dy*16oc*8 = 6144 floats
    const int tid  = threadIdx.x;
    const int ocq  = tid >> 5;        // warp id = 4-oc group (uniform)
    const int lane = tid & 31;
    const int row  = lane >> 1;       // 0..15
    const int xh   = lane & 1;        // x half: 0 or 1 (8 px each)

    // ---- fill input tile: 16c x 18 rows x 20 cols (halo), skewed ----
    for (int idx = tid; idx < 5760; idx += 128) {
        int c  = idx / 360; int r0 = idx - c*360;
        int rr = r0 / 20;   int xx = r0 - rr*20;
        int gy = rr - 1, gx = xx - 1;
        float v = 0.f;
        if ((unsigned)gy < 16u && (unsigned)gx < 16u)
            v = in[((b*CIN + cb + c)*16 + gy)*16 + gx];
        in_s[c*IN_PITCH + rr*20 + 2*((rr >> 1) & 1) + xx] = v;
    }
    // ---- fill weights: group [(c*3+dy)*16+oc]*8 = [w0,w0,w1,w1,w2,w2,pad,pad] ----
    for (int idx = tid; idx < 2304; idx += 128) {
        int dx   = idx % 3;
        int rest = idx / 3;            // (c*3+dy)*16 + oc
        int oc   = rest & 15;
        int cd   = rest >> 4;          // c*3 + dy
        int c    = cd / 3, dy = cd - c*3;
        float w = W[(oc0 + oc)*CIN*9 + (cb + c)*9 + dy*3 + dx];
        w_s[rest*8 + dx*2]     = w;
        w_s[rest*8 + dx*2 + 1] = w;
    }
    __syncthreads();

    uint64_t acc[4][4];
    #pragma unroll
    for (int o = 0; o < 4; o++)
        #pragma unroll
        for (int k = 0; k < 4; k++) acc[o][k] = pk2(0.f, 0.f);

    const float* crow0 = in_s + xh*8;

    #pragma unroll 1
    for (int c = 0; c < 16; c++) {
        const float* crow = crow0 + c*IN_PITCH;
        const float* wc   = w_s + (c*3*16 + ocq*4)*8;
        #pragma unroll
        for (int dy = 0; dy < 3; dy++) {
            int r = row + dy;
            const uint64_t* rp = (const uint64_t*)(crow + r*20 + 2*((r >> 1) & 1));
            uint64_t E0 = rp[0], E1 = rp[1], E2 = rp[2], E3 = rp[3], E4 = rp[4];
            float a0,a1,a2,a3,a4,a5,a6,a7,a8,a9;
            upk(E0,a0,a1); upk(E1,a2,a3); upk(E2,a4,a5); upk(E3,a6,a7); upk(E4,a8,a9);
            uint64_t D0 = pk2(a1,a2), D1 = pk2(a3,a4), D2 = pk2(a5,a6), D3 = pk2(a7,a8);
            const float* wd = wc + dy*128;   // 16 oc * 8 floats
            #pragma unroll
            for (int ol = 0; ol < 4; ol++) {
                const float* wb = wd + ol*8;
                ulonglong2 ww = *(const ulonglong2*)wb;   // (w0,w0),(w1,w1)
                uint64_t  W2 = ((const uint64_t*)wb)[2];  // (w2,w2)
                fma2(acc[ol][0], E0, ww.x); fma2(acc[ol][0], D0, ww.y); fma2(acc[ol][0], E1, W2);
                fma2(acc[ol][1], E1, ww.x); fma2(acc[ol][1], D1, ww.y); fma2(acc[ol][1], E2, W2);
                fma2(acc[ol][2], E2, ww.x); fma2(acc[ol][2], D2, ww.y); fma2(acc[ol][2], E3, W2);
                fma2(acc[ol][3], E3, ww.x); fma2(acc[ol][3], D3, ww.y); fma2(acc[ol][3], E4, W2);
            }
        }
    }
    #pragma unroll
    for (int ol = 0; ol < 4; ol++) {
        int oc = oc0 + ocq*4 + ol;
        float4 r0, r1;
        upk(acc[ol][0], r0.x, r0.y); upk(acc[ol][1], r0.z, r0.w);
        upk(acc[ol][2], r1.x, r1.y); upk(acc[ol][3], r1.z, r1.w);
        float4* dp = (float4*)&slab[((b*128 + oc)*16 + row)*16 + xh*8];
        dp[0] = r0; dp[1] = r1;
    }
}

// ---------------- conv1 tile (3 in-ch, 32x32), 8 units of 128 ----------------
__device__ __forceinline__ void conv1_tile(
    const float* __restrict__ s, const float* __restrict__ W1,
    float* __restrict__ slab, int tile, float* sm)
{
    int tid = threadIdx.x;
    for (int idx = tid; idx < 1728; idx += 128) sm[idx] = W1[idx];
    __syncthreads();
    #pragma unroll 1
    for (int k8 = 0; k8 < 8; k8++) {
        int u   = tile*1024 + k8*128 + tid;
        int row = u >> 2;
        int xb  = (u & 3) * 8;
        int b   = row >> 11;
        int oc  = (row >> 5) & 63;
        int y   = row & 31;
        float acc[8];
        #pragma unroll
        for (int i = 0; i < 8; i++) acc[i] = 0.f;
        #pragma unroll
        for (int c = 0; c < 3; c++) {
            #pragma unroll
            for (int dy = 0; dy < 3; dy++) {
                int gy = y + dy - 1;
                if ((unsigned)gy >= 32u) continue;
                const float* srow = s + ((b*3 + c)*32 + gy)*32;
                float iv[10];
                #pragma unroll
                for (int t = 0; t < 10; t++) {
                    int gx = xb + t - 1;
                    iv[t] = ((unsigned)gx < 32u) ? srow[gx] : 0.f;
                }
                float w[3];
                #pragma unroll
                for (int dx = 0; dx < 3; dx++) w[dx] = sm[oc*27 + c*9 + dy*3 + dx];
                #pragma unroll
                for (int i = 0; i < 8; i++)
                    #pragma unroll
                    for (int dx = 0; dx < 3; dx++)
                        acc[i] += iv[i + dx] * w[dx];
            }
        }
        int base = ((b*64 + oc)*32 + y)*32 + xb;
        #pragma unroll
        for (int i = 0; i < 8; i++) slab[base + i] = acc[i];
    }
}

// ---------------- FC tile (128 thr): out[b,j] = A[b,k0:k0+256].W[j,k0:k0+256] ----------------
__device__ __forceinline__ void fc_tile(
    const float* __restrict__ A, const float* __restrict__ W,
    float* __restrict__ out, int K, int j0, int k0, float* sm)
{
    float* fs = sm;          // [16][64]
    float* ws = sm + 1024;   // [64][65]
    int tid = threadIdx.x;
    int tj  = tid & 31;      // 2 j each -> 64 j
    int tb  = tid >> 5;      // 0..3, 4 b each (strided by 4)
    float acc[2][4] = {{0.f,0.f,0.f,0.f},{0.f,0.f,0.f,0.f}};
    #pragma unroll 1
    for (int kc = k0; kc < k0 + 256; kc += 64) {
        __syncthreads();
        for (int idx = tid; idx < 1024; idx += 128) {
            int bb = idx >> 6, kk = idx & 63;
            fs[idx] = A[bb*K + kc + kk];
        }
        for (int idx = tid; idx < 4096; idx += 128) {
            int jl = idx >> 6, kk = idx & 63;
            ws[jl*65 + kk] = W[(j0 + jl)*K + kc + kk];
        }
        __syncthreads();
        #pragma unroll 4
        for (int kk = 0; kk < 64; kk++) {
            float w0 = ws[(tj*2    )*65 + kk];
            float w1 = ws[(tj*2 + 1)*65 + kk];
            #pragma unroll
            for (int r = 0; r < 4; r++) {
                float f = fs[(tb + r*4)*64 + kk];
                acc[0][r] += w0*f;
                acc[1][r] += w1*f;
            }
        }
    }
    #pragma unroll
    for (int q = 0; q < 2; q++)
        #pragma unroll
        for (int r = 0; r < 4; r++)
            out[(tb + r*4)*1024 + (j0 + tj*2 + q)] = acc[q][r];
}

// ---------------- fc3: mo += o5 @ L3^T (single tile, deterministic) ----------------
__device__ __forceinline__ void fc3_part(
    const float* __restrict__ o5, const float* __restrict__ L3, float* __restrict__ mo)
{
    #pragma unroll
    for (int pass = 0; pass < 2; pass++) {
        int t = threadIdx.x + pass*128;
        if (t < 160) {
            int b = t / 10, j = t - b*10;
            const float* a = o5 + b*1024;
            const float* w = L3 + j*1024;
            float acc = 0.f;
            #pragma unroll 4
            for (int k = 0; k < 1024; k++) acc += a[k]*w[k];
            mo[t] += acc;
        }
    }
}

// ---------------- fat per-step kernel: work queue over 2241 tiles ----------------
__global__ void __launch_bounds__(128, 4) conv_step(
    const float* __restrict__ W1, const float* __restrict__ W2,
    const float* __restrict__ W3, const float* __restrict__ L1,
    const float* __restrict__ L2, const float* __restrict__ L3)
{
    __shared__ __align__(16) float sm[12032];
    __shared__ int s_tile;
    for (;;) {
        __syncthreads();
        if (threadIdx.x == 0) s_tile = atomicAdd(&g_tick, 1);
        __syncthreads();
        int t = s_tile;
        if (t >= NT) return;
        if (t < 1024) {                      // conv3: 16b x 8ocg x 8ks
            int ks = t & 7, ocg = (t >> 3) & 7, b = t >> 6;
            conv_tile(g_o2, W3, &g_s3[ks][0], 128, ks*16, b, ocg*16, sm);
        } else if (t < 1536) {               // conv2: 16b x 8ocg x 4ks
            int i = t - 1024;
            int ks = i & 3, ocg = (i >> 2) & 7, b = i >> 5;
            conv_tile(g_o1p, W2, &g_s2[ks][0], 64, ks*16, b, ocg*16, sm);
        } else if (t < 2048) {               // fc1: 16jg x 32ks
            int i = t - 1536;
            int jg = i & 15, ks = i >> 4;
            fc_tile(g_f, L1, &g_s4[ks][0], 8192, jg*64, ks*256, sm);
        } else if (t < 2176) {               // conv1: 128 tiles
            conv1_tile(g_s, W1, g_c1s, t - 2048, sm);
        } else if (t < 2240) {               // fc2: 16jg x 4ks
            int i = t - 2176;
            int jg = i & 15, ks = i >> 4;
            fc_tile(g_o4, L2, &g_s5[ks][0], 1024, jg*64, ks*256, sm);
        } else {                             // fc3
            fc3_part(g_o5, L3, g_mo);
        }
    }
}

__global__ void write_out(float* __restrict__ out) {
    int t = threadIdx.x;
    if (t < 160) out[t] = g_mo[t];
}

extern "C" void kernel_launch(void* const* d_in, const int* in_sizes, int n_in,
                              void* d_out, int out_size)
{
    const float* x  = (const float*)d_in[0];
    const float* W1 = (const float*)d_in[1];
    const float* W2 = (const float*)d_in[2];
    const float* W3 = (const float*)d_in[3];
    const float* L1 = (const float*)d_in[4];
    const float* L2 = (const float*)d_in[5];
    const float* L3 = (const float*)d_in[6];

    zero_state<<<512, 256>>>();
    nop_k<<<1, 32>>>();
    for (int t = 0; t < T_STEPS; t++) {
        spike_step<<<3904, 256>>>(x);
        conv_step<<<GRID_CONV, 128>>>(W1, W2, W3, L1, L2, L3);
    }
    write_out<<<1, 192>>>((float*)d_out);
}

// round 6
// speedup vs baseline: 1.3310x; 1.3310x over previous
#include <cuda_runtime.h>
#include <cstdint>

#define BB 16
#define T_STEPS 20
#define NT 1953
#define GRID_CONV 592

// ---------------- persistent device state ----------------
__device__ float g_v [BB*3*32*32];
__device__ float g_s [BB*3*32*32];
__device__ float g_m1[BB*64*32*32];
__device__ float g_o1[BB*64*32*32];
__device__ float g_o1p[BB*64*16*16];
__device__ float g_m2[BB*128*16*16];
__device__ float g_o2[BB*128*16*16];
__device__ float g_m3[BB*128*16*16];
__device__ float g_o3[BB*128*16*16];
__device__ float g_f [BB*8192];
__device__ float g_m4[BB*1024];
__device__ float g_o4[BB*1024];
__device__ float g_m5[BB*1024];
__device__ float g_o5[BB*1024];
__device__ float g_mo[BB*10];
__device__ int   g_tick;

// ---------------- partial-sum slabs (deterministic K-split) ----------------
__device__ float g_c1s[BB*64*32*32];        // conv1 raw out
__device__ float g_s2 [4][BB*128*16*16];    // conv2: 4 cin-splits
__device__ float g_s3 [8][BB*128*16*16];    // conv3: 8 cin-splits
__device__ float g_s4 [32][BB*1024];        // fc1: 32 k-splits
__device__ float g_s5 [4][BB*1024];         // fc2: 4 k-splits

// ---------------- f32x2 helpers ----------------
__device__ __forceinline__ uint64_t pk2(float lo, float hi) {
    uint64_t r; asm("mov.b64 %0, {%1, %2};" : "=l"(r) : "f"(lo), "f"(hi)); return r;
}
__device__ __forceinline__ void upk(uint64_t v, float& lo, float& hi) {
    asm("mov.b64 {%0, %1}, %2;" : "=f"(lo), "=f"(hi) : "l"(v));
}
__device__ __forceinline__ void fma2(uint64_t& d, uint64_t a, uint64_t b) {
    asm("fma.rn.f32x2 %0, %1, %2, %0;" : "+l"(d) : "l"(a), "l"(b));
}

// ---------------- zero state ----------------
__global__ void zero_state() {
    int n  = gridDim.x * blockDim.x;
    int i0 = blockIdx.x * blockDim.x + threadIdx.x;
    for (int i = i0; i < BB*3*32*32;   i += n) { g_v[i] = 0.f; g_s[i] = 0.f; }
    for (int i = i0; i < BB*64*32*32;  i += n) { g_m1[i] = 0.f; g_o1[i] = 0.f; g_c1s[i] = 0.f; }
    for (int i = i0; i < BB*128*16*16; i += n) {
        g_m2[i] = 0.f; g_o2[i] = 0.f; g_m3[i] = 0.f; g_o3[i] = 0.f;
        #pragma unroll
        for (int k = 0; k < 4; k++) g_s2[k][i] = 0.f;
        #pragma unroll
        for (int k = 0; k < 8; k++) g_s3[k][i] = 0.f;
    }
    for (int i = i0; i < BB*1024; i += n) {
        g_m4[i] = 0.f; g_o4[i] = 0.f; g_m5[i] = 0.f; g_o5[i] = 0.f;
        #pragma unroll
        for (int k = 0; k < 32; k++) g_s4[k][i] = 0.f;
        #pragma unroll
        for (int k = 0; k < 4;  k++) g_s5[k][i] = 0.f;
    }
    for (int i = i0; i < BB*10; i += n) g_mo[i] = 0.f;
}

// keeps ncu -s 5 aligned onto a conv_step launch
__global__ void nop_k() {}

// ---------------- per-step spike kernel: membrane completion + thresholds ----------------
__global__ void __launch_bounds__(256) spike_step(const float* __restrict__ x) {
    int i = blockIdx.x * 256 + threadIdx.x;
    if (i == 0) g_tick = 0;
    if (i < 49152) {
        float v = g_v[i] + x[i];
        v = v - g_s[i];
        g_v[i] = v;
        g_s[i] = (v > 1.0f) ? 1.0f : 0.0f;
    } else if (i < 311296) {
        int p  = i - 49152;                  // (B*64, 16, 16) pooled
        int px = p & 15, py = (p >> 4) & 15, bc = p >> 8;
        int base = (bc*32 + py*2)*32 + px*2;
        float sum = 0.f;
        #pragma unroll
        for (int dy = 0; dy < 2; dy++)
            #pragma unroll
            for (int dx = 0; dx < 2; dx++) {
                int idx = base + dy*32 + dx;
                float m = (g_m1[idx] + g_c1s[idx]) - g_o1[idx];
                float o = (m > 1.0f) ? 1.0f : 0.0f;
                g_m1[idx] = m;
                g_o1[idx] = o;
                sum += o;
            }
        g_o1p[p] = sum * 0.25f;
    } else if (i < 835584) {
        int p = i - 311296;
        float inp = ((g_s2[0][p] + g_s2[1][p]) + g_s2[2][p]) + g_s2[3][p];
        float m = (g_m2[p] + inp) - g_o2[p];
        g_m2[p] = m;
        g_o2[p] = (m > 1.0f) ? 1.0f : 0.0f;
    } else if (i < 966656) {
        int p  = i - 835584;                 // (B*128, 8, 8) pooled
        int px = p & 7, py = (p >> 3) & 7, bc = p >> 6;
        int base = (bc*16 + py*2)*16 + px*2;
        float sum = 0.f;
        #pragma unroll
        for (int dy = 0; dy < 2; dy++)
            #pragma unroll
            for (int dx = 0; dx < 2; dx++) {
                int idx = base + dy*16 + dx;
                float inp = 0.f;
                #pragma unroll
                for (int k = 0; k < 8; k++) inp += g_s3[k][idx];
                float m = (g_m3[idx] + inp) - g_o3[idx];
                float o = (m > 1.0f) ? 1.0f : 0.0f;
                g_m3[idx] = m;
                g_o3[idx] = o;
                sum += o;
            }
        int b = bc >> 7, c = bc & 127;
        g_f[b*8192 + c*64 + py*8 + px] = sum * 0.25f;
    } else if (i < 983040) {
        int p = i - 966656;
        float inp = 0.f;
        #pragma unroll 8
        for (int k = 0; k < 32; k++) inp += g_s4[k][p];
        float m = (g_m4[p] + inp) - g_o4[p];
        g_m4[p] = m;
        g_o4[p] = (m > 1.0f) ? 1.0f : 0.0f;
    } else if (i < 999424) {
        int p = i - 983040;
        float inp = ((g_s5[0][p] + g_s5[1][p]) + g_s5[2][p]) + g_s5[3][p];
        float m = (g_m5[p] + inp) - g_o5[p];
        g_m5[p] = m;
        g_o5[p] = (m > 1.0f) ? 1.0f : 0.0f;
    }
}

// ---------------- conv tile: 16 oc x full 16x16 image x 16 cin ----------------
// 256 threads = 8 warps. warp = oc-quad (ocq = wid>>1) x row band (wid&1).
// lane: yl = sg&7 (row in band), xq = sg>>3 (4-px group). thread = 4 oc x 4 px.
// Input smem: 16c x 18rows x 20cols, skew +6 floats on odd rows; per half-warp
// the 16 LDS.64 unit-indices tile {0..15} mod 16 -> conflict-free.
// Weights: dup pairs in 8-float groups [(c*3+dy)*16+oc]*8 = [w0,w0,w1,w1,w2,w2,-,-]
// -> per oc one LDS.128 + one LDS.64, warp-uniform broadcast.
#define IN_PITCH 368
__device__ __forceinline__ void conv_tile(
    const float* __restrict__ in, const float* __restrict__ W,
    float* __restrict__ slab, int CIN, int cb, int b, int oc0, float* sm)
{
    float* in_s = sm;                 // 16 * 368 = 5888 floats
    float* w_s  = sm + 5888;          // 16c*3dy*16oc*8 = 6144 floats
    const int tid  = threadIdx.x;
    const int wid  = tid >> 5;
    const int ocq  = wid >> 1;        // 0..3 (warp-uniform oc quad)
    const int band = wid & 1;         // 0..1 (8-row band)
    const int sg   = tid & 31;
    const int yl   = sg & 7;
    const int xq   = sg >> 3;
    const int xb   = xq * 4;
    const int row  = band*8 + yl;

    // ---- fill input tile: 16c x 18 x 20 (halo), skewed ----
    for (int idx = tid; idx < 5760; idx += 256) {
        int c  = idx / 360; int r0 = idx - c*360;
        int rr = r0 / 20;   int xx = r0 - rr*20;
        int gy = rr - 1, gx = xx - 1;
        float v = 0.f;
        if ((unsigned)gy < 16u && (unsigned)gx < 16u)
            v = in[((b*CIN + cb + c)*16 + gy)*16 + gx];
        in_s[c*IN_PITCH + rr*20 + 6*(rr & 1) + xx] = v;
    }
    // ---- fill weights ----
    for (int idx = tid; idx < 2304; idx += 256) {
        int dx   = idx % 3;
        int q    = idx / 3;            // (c*3+dy)*16... decode: oc = q&15, cd = q>>4
        int oc   = q & 15;
        int cd   = q >> 4;             // 0..47 = c*3+dy
        int c    = cd / 3, dy = cd - c*3;
        float w = W[(oc0 + oc)*CIN*9 + (cb + c)*9 + dy*3 + dx];
        int g = ((c*3 + dy)*16 + oc)*8 + dx*2;
        w_s[g]     = w;
        w_s[g + 1] = w;
    }
    __syncthreads();

    uint64_t acc[4][2];
    #pragma unroll
    for (int o = 0; o < 4; o++) { acc[o][0] = pk2(0.f,0.f); acc[o][1] = pk2(0.f,0.f); }

    // precompute per-thread row offsets (c-independent)
    const int off0 = (row    )*20 + 6*((row    ) & 1) + xb;
    const int off1 = (row + 1)*20 + 6*((row + 1) & 1) + xb;
    const int off2 = (row + 2)*20 + 6*((row + 2) & 1) + xb;

    #pragma unroll 1
    for (int c = 0; c < 16; c++) {
        const float* cin = in_s + c*IN_PITCH;
        const float* wc  = w_s + c*384 + ocq*32;    // (c*3*16 + ocq*4)*8
        #pragma unroll
        for (int dy = 0; dy < 3; dy++) {
            const int off = (dy == 0) ? off0 : (dy == 1) ? off1 : off2;
            const uint64_t* rp = (const uint64_t*)(cin + off);
            uint64_t E0 = rp[0], E1 = rp[1], E2 = rp[2];
            float a0,a1,a2,a3,a4,a5;
            upk(E0,a0,a1); upk(E1,a2,a3); upk(E2,a4,a5);
            uint64_t D0 = pk2(a1,a2), D1 = pk2(a3,a4);
            const float* wd = wc + dy*128;
            #pragma unroll
            for (int ol = 0; ol < 4; ol++) {
                ulonglong2 ww = *(const ulonglong2*)(wd + ol*8);  // (w0,w0),(w1,w1)
                uint64_t  W2  = *(const uint64_t*)(wd + ol*8 + 4); // (w2,w2)
                fma2(acc[ol][0], E0, ww.x); fma2(acc[ol][0], D0, ww.y); fma2(acc[ol][0], E1, W2);
                fma2(acc[ol][1], E1, ww.x); fma2(acc[ol][1], D1, ww.y); fma2(acc[ol][1], E2, W2);
            }
        }
    }
    #pragma unroll
    for (int ol = 0; ol < 4; ol++) {
        int oc = oc0 + ocq*4 + ol;
        float4 r;
        upk(acc[ol][0], r.x, r.y);
        upk(acc[ol][1], r.z, r.w);
        *(float4*)&slab[((b*128 + oc)*16 + row)*16 + xb] = r;
    }
}

// ---------------- conv1 tile (3 in-ch, 32x32), 4 units of 256 ----------------
__device__ __forceinline__ void conv1_tile(
    const float* __restrict__ s, const float* __restrict__ W1,
    float* __restrict__ slab, int tile, float* sm)
{
    int tid = threadIdx.x;
    for (int idx = tid; idx < 1728; idx += 256) sm[idx] = W1[idx];
    __syncthreads();
    #pragma unroll 1
    for (int u4 = 0; u4 < 4; u4++) {
        int u   = (tile*4 + u4)*256 + tid;
        int row = u >> 2;
        int xb  = (u & 3) * 8;
        int b   = row >> 11;
        int oc  = (row >> 5) & 63;
        int y   = row & 31;
        float acc[8];
        #pragma unroll
        for (int i = 0; i < 8; i++) acc[i] = 0.f;
        #pragma unroll
        for (int c = 0; c < 3; c++) {
            #pragma unroll
            for (int dy = 0; dy < 3; dy++) {
                int gy = y + dy - 1;
                if ((unsigned)gy >= 32u) continue;
                const float* srow = s + ((b*3 + c)*32 + gy)*32;
                float iv[10];
                #pragma unroll
                for (int t = 0; t < 10; t++) {
                    int gx = xb + t - 1;
                    iv[t] = ((unsigned)gx < 32u) ? srow[gx] : 0.f;
                }
                float w[3];
                #pragma unroll
                for (int dx = 0; dx < 3; dx++) w[dx] = sm[oc*27 + c*9 + dy*3 + dx];
                #pragma unroll
                for (int i = 0; i < 8; i++)
                    #pragma unroll
                    for (int dx = 0; dx < 3; dx++)
                        acc[i] += iv[i + dx] * w[dx];
            }
        }
        int base = ((b*64 + oc)*32 + y)*32 + xb;
        #pragma unroll
        for (int i = 0; i < 8; i++) slab[base + i] = acc[i];
    }
}

// ---------------- FC tile: 128 j x 16 b x 256 k, f32x2 ----------------
// warp: bq = wid&3 (4 b), jh = wid>>2 (64-j half). lane: j-pair 2*tj.
// ws transposed [kk][128 j] pad 130 (coalesced LDS.64 per j-pair);
// fs dup pairs [kk][16b*2] (broadcast LDS.128 = 2 b).
__device__ __forceinline__ void fc_tile(
    const float* __restrict__ A, const float* __restrict__ W,
    float* __restrict__ out, int K, int j0, int k0, float* sm)
{
    float* fs = sm;          // 64 kk * 32 = 2048
    float* ws = sm + 2048;   // 64 kk * 130 = 8320
    const int tid = threadIdx.x;
    const int wid = tid >> 5;
    const int bq  = wid & 3;
    const int jh  = wid >> 2;
    const int tj  = tid & 31;

    uint64_t acc[4];
    #pragma unroll
    for (int r = 0; r < 4; r++) acc[r] = pk2(0.f, 0.f);

    #pragma unroll 1
    for (int kc = k0; kc < k0 + 256; kc += 64) {
        __syncthreads();
        for (int idx = tid; idx < 1024; idx += 256) {
            int bb = idx & 15, kk = idx >> 4;
            float v = A[bb*K + kc + kk];
            fs[kk*32 + bb*2]     = v;
            fs[kk*32 + bb*2 + 1] = v;
        }
        for (int idx = tid; idx < 8192; idx += 256) {
            int jl = idx >> 6, kk = idx & 63;
            ws[kk*130 + jl] = W[(j0 + jl)*K + kc + kk];
        }
        __syncthreads();
        #pragma unroll 4
        for (int kk = 0; kk < 64; kk++) {
            uint64_t wj = *(const uint64_t*)(ws + kk*130 + jh*64 + tj*2);
            const ulonglong2* fp = (const ulonglong2*)(fs + kk*32 + bq*8);
            ulonglong2 f01 = fp[0], f23 = fp[1];
            fma2(acc[0], wj, f01.x);
            fma2(acc[1], wj, f01.y);
            fma2(acc[2], wj, f23.x);
            fma2(acc[3], wj, f23.y);
        }
    }
    int j = j0 + jh*64 + tj*2;
    #pragma unroll
    for (int r = 0; r < 4; r++) {
        int bb = bq*4 + r;
        float lo, hi; upk(acc[r], lo, hi);
        *(float2*)&out[bb*1024 + j] = make_float2(lo, hi);
    }
}

// ---------------- fc3: mo += o5 @ L3^T (single tile, deterministic) ----------------
__device__ __forceinline__ void fc3_part(
    const float* __restrict__ o5, const float* __restrict__ L3, float* __restrict__ mo)
{
    int t = threadIdx.x;
    if (t >= 160) return;
    int b = t / 10, j = t - b*10;
    const float* a = o5 + b*1024;
    const float* w = L3 + j*1024;
    float acc = 0.f;
    #pragma unroll 4
    for (int k = 0; k < 1024; k++) acc += a[k]*w[k];
    mo[t] += acc;
}

// ---------------- fat per-step kernel: work queue over 1953 tiles ----------------
__global__ void __launch_bounds__(256, 4) conv_step(
    const float* __restrict__ W1, const float* __restrict__ W2,
    const float* __restrict__ W3, const float* __restrict__ L1,
    const float* __restrict__ L2, const float* __restrict__ L3)
{
    __shared__ __align__(16) float sm[12032];
    __shared__ int s_tile;
    for (;;) {
        __syncthreads();
        if (threadIdx.x == 0) s_tile = atomicAdd(&g_tick, 1);
        __syncthreads();
        int t = s_tile;
        if (t >= NT) return;
        if (t < 1024) {                      // conv3: 16b x 8ocg x 8ks
            int ks = t & 7, ocg = (t >> 3) & 7, b = t >> 6;
            conv_tile(g_o2, W3, &g_s3[ks][0], 128, ks*16, b, ocg*16, sm);
        } else if (t < 1536) {               // conv2: 16b x 8ocg x 4ks
            int i = t - 1024;
            int ks = i & 3, ocg = (i >> 2) & 7, b = i >> 5;
            conv_tile(g_o1p, W2, &g_s2[ks][0], 64, ks*16, b, ocg*16, sm);
        } else if (t < 1792) {               // fc1: 8jg x 32ks
            int i = t - 1536;
            int jg = i & 7, ks = i >> 3;
            fc_tile(g_f, L1, &g_s4[ks][0], 8192, jg*128, ks*256, sm);
        } else if (t < 1920) {               // conv1: 128 tiles
            conv1_tile(g_s, W1, g_c1s, t - 1792, sm);
        } else if (t < 1952) {               // fc2: 8jg x 4ks
            int i = t - 1920;
            int jg = i & 7, ks = i >> 3;
            fc_tile(g_o4, L2, &g_s5[ks][0], 1024, jg*128, ks*256, sm);
        } else {                             // fc3
            fc3_part(g_o5, L3, g_mo);
        }
    }
}

__global__ void write_out(float* __restrict__ out) {
    int t = threadIdx.x;
    if (t < 160) out[t] = g_mo[t];
}

extern "C" void kernel_launch(void* const* d_in, const int* in_sizes, int n_in,
                              void* d_out, int out_size)
{
    const float* x  = (const float*)d_in[0];
    const float* W1 = (const float*)d_in[1];
    const float* W2 = (const float*)d_in[2];
    const float* W3 = (const float*)d_in[3];
    const float* L1 = (const float*)d_in[4];
    const float* L2 = (const float*)d_in[5];
    const float* L3 = (const float*)d_in[6];

    zero_state<<<512, 256>>>();
    nop_k<<<1, 32>>>();
    for (int t = 0; t < T_STEPS; t++) {
        spike_step<<<3904, 256>>>(x);
        conv_step<<<GRID_CONV, 256>>>(W1, W2, W3, L1, L2, L3);
    }
    write_out<<<1, 192>>>((float*)d_out);
}

// round 7
// speedup vs baseline: 1.4029x; 1.0540x over previous
#include <cuda_runtime.h>
#include <cstdint>

#define BB 16
#define T_STEPS 20
#define NT 3777
#define GRID_CONV 592

// ---------------- persistent device state ----------------
__device__ float g_v [BB*3*32*32];
__device__ float g_s [BB*3*32*32];
__device__ float g_m1[BB*64*32*32];
__device__ float g_o1[BB*64*32*32];
__device__ float g_o1p[BB*64*16*16];
__device__ float g_m2[BB*128*16*16];
__device__ float g_o2[BB*128*16*16];
__device__ float g_m3[BB*128*16*16];
__device__ float g_o3[BB*128*16*16];
__device__ float g_f [BB*8192];
__device__ float g_m4[BB*1024];
__device__ float g_o4[BB*1024];
__device__ float g_m5[BB*1024];
__device__ float g_o5[BB*1024];
__device__ float g_mo[BB*10];
__device__ int   g_tick;

// ---------------- partial-sum slabs (deterministic K-split) ----------------
__device__ float g_c1s[BB*64*32*32];        // conv1 raw out
__device__ float g_s2 [4][BB*128*16*16];    // conv2: 4 cin-splits
__device__ float g_s3 [8][BB*128*16*16];    // conv3: 8 cin-splits
__device__ float g_s4 [32][BB*1024];        // fc1: 32 k-splits
__device__ float g_s5 [4][BB*1024];         // fc2: 4 k-splits

// ---------------- f32x2 helpers ----------------
__device__ __forceinline__ uint64_t pk2(float lo, float hi) {
    uint64_t r; asm("mov.b64 %0, {%1, %2};" : "=l"(r) : "f"(lo), "f"(hi)); return r;
}
__device__ __forceinline__ void upk(uint64_t v, float& lo, float& hi) {
    asm("mov.b64 {%0, %1}, %2;" : "=f"(lo), "=f"(hi) : "l"(v));
}
__device__ __forceinline__ void fma2(uint64_t& d, uint64_t a, uint64_t b) {
    asm("fma.rn.f32x2 %0, %1, %2, %0;" : "+l"(d) : "l"(a), "l"(b));
}

// ---------------- zero state ----------------
__global__ void zero_state() {
    int n  = gridDim.x * blockDim.x;
    int i0 = blockIdx.x * blockDim.x + threadIdx.x;
    for (int i = i0; i < BB*3*32*32;   i += n) { g_v[i] = 0.f; g_s[i] = 0.f; }
    for (int i = i0; i < BB*64*32*32;  i += n) { g_m1[i] = 0.f; g_o1[i] = 0.f; g_c1s[i] = 0.f; }
    for (int i = i0; i < BB*128*16*16; i += n) {
        g_m2[i] = 0.f; g_o2[i] = 0.f; g_m3[i] = 0.f; g_o3[i] = 0.f;
        #pragma unroll
        for (int k = 0; k < 4; k++) g_s2[k][i] = 0.f;
        #pragma unroll
        for (int k = 0; k < 8; k++) g_s3[k][i] = 0.f;
    }
    for (int i = i0; i < BB*1024; i += n) {
        g_m4[i] = 0.f; g_o4[i] = 0.f; g_m5[i] = 0.f; g_o5[i] = 0.f;
        #pragma unroll
        for (int k = 0; k < 32; k++) g_s4[k][i] = 0.f;
        #pragma unroll
        for (int k = 0; k < 4;  k++) g_s5[k][i] = 0.f;
    }
    for (int i = i0; i < BB*10; i += n) g_mo[i] = 0.f;
}

// keeps ncu -s 5 aligned onto a conv_step launch
__global__ void nop_k() {}

// ---------------- per-step spike kernel: membrane completion + thresholds ----------------
__global__ void __launch_bounds__(256) spike_step(const float* __restrict__ x) {
    int i = blockIdx.x * 256 + threadIdx.x;
    if (i == 0) g_tick = 0;
    if (i < 49152) {
        float v = g_v[i] + x[i];
        v = v - g_s[i];
        g_v[i] = v;
        g_s[i] = (v > 1.0f) ? 1.0f : 0.0f;
    } else if (i < 311296) {
        int p  = i - 49152;                  // (B*64, 16, 16) pooled
        int px = p & 15, py = (p >> 4) & 15, bc = p >> 8;
        int base = (bc*32 + py*2)*32 + px*2;
        float sum = 0.f;
        #pragma unroll
        for (int dy = 0; dy < 2; dy++)
            #pragma unroll
            for (int dx = 0; dx < 2; dx++) {
                int idx = base + dy*32 + dx;
                float m = (g_m1[idx] + g_c1s[idx]) - g_o1[idx];
                float o = (m > 1.0f) ? 1.0f : 0.0f;
                g_m1[idx] = m;
                g_o1[idx] = o;
                sum += o;
            }
        g_o1p[p] = sum * 0.25f;
    } else if (i < 835584) {
        int p = i - 311296;
        float inp = ((g_s2[0][p] + g_s2[1][p]) + g_s2[2][p]) + g_s2[3][p];
        float m = (g_m2[p] + inp) - g_o2[p];
        g_m2[p] = m;
        g_o2[p] = (m > 1.0f) ? 1.0f : 0.0f;
    } else if (i < 966656) {
        int p  = i - 835584;                 // (B*128, 8, 8) pooled
        int px = p & 7, py = (p >> 3) & 7, bc = p >> 6;
        int base = (bc*16 + py*2)*16 + px*2;
        float sum = 0.f;
        #pragma unroll
        for (int dy = 0; dy < 2; dy++)
            #pragma unroll
            for (int dx = 0; dx < 2; dx++) {
                int idx = base + dy*16 + dx;
                float inp = 0.f;
                #pragma unroll
                for (int k = 0; k < 8; k++) inp += g_s3[k][idx];
                float m = (g_m3[idx] + inp) - g_o3[idx];
                float o = (m > 1.0f) ? 1.0f : 0.0f;
                g_m3[idx] = m;
                g_o3[idx] = o;
                sum += o;
            }
        int b = bc >> 7, c = bc & 127;
        g_f[b*8192 + c*64 + py*8 + px] = sum * 0.25f;
    } else if (i < 983040) {
        int p = i - 966656;
        float inp = 0.f;
        #pragma unroll 8
        for (int k = 0; k < 32; k++) inp += g_s4[k][p];
        float m = (g_m4[p] + inp) - g_o4[p];
        g_m4[p] = m;
        g_o4[p] = (m > 1.0f) ? 1.0f : 0.0f;
    } else if (i < 999424) {
        int p = i - 983040;
        float inp = ((g_s5[0][p] + g_s5[1][p]) + g_s5[2][p]) + g_s5[3][p];
        float m = (g_m5[p] + inp) - g_o5[p];
        g_m5[p] = m;
        g_o5[p] = (m > 1.0f) ? 1.0f : 0.0f;
    }
}

// ---------------- conv tile: 16 oc x 8 rows x 16 cols x 16 cin ----------------
// R4 thread layout (proven best): 8 warps; warp = oc-pair; lane: yl = sg&7,
// xq = sg>>3 (4-px group). Thread = 2 oc x 4 px.
// Fills are division-free (shift/mask only). Weights stored as dup pairs in
// (c,dy)-grouped 8-float blocks [w0,w0,w1,w1,w2,w2,-,-] -> per (c,dy) per warp:
// 2x LDS.128 + 2x LDS.64 (warp-uniform broadcast).
// Input smem: 16c x 10 rows x 20 cols, skew +6 floats on odd rows;
// per half-warp the 16 LDS.64 unit-indices are distinct mod 16 -> conflict-free.
#define IN_PITCH 208
__device__ __forceinline__ void conv_tile(
    const float* __restrict__ in, const float* __restrict__ W,
    float* __restrict__ slab, int CIN, int cb, int b, int oc0, int y0, float* sm)
{
    float* in_s = sm;                 // 16*208 = 3328 floats
    float* w_s  = sm + 3328;          // 16c*3dy*16oc*8 = 6144 floats
    const int tid = threadIdx.x;
    const int wid = tid >> 5;         // oc-pair 0..7 (warp-uniform)
    const int sg  = tid & 31;
    const int yl  = sg & 7;
    const int xq  = sg >> 3;
    const int xb  = xq * 4;

    // ---- phase A: zero in_s (float4) + weight fill (disjoint regions) ----
    {
        float4 z = make_float4(0.f, 0.f, 0.f, 0.f);
        float4* p = (float4*)in_s;
        #pragma unroll
        for (int k = 0; k < 4; k++) {
            int i = tid + k*256;
            if (i < 832) p[i] = z;
        }
    }
    {
        int oc = tid >> 4, c = tid & 15;
        const float* src = W + (oc0 + oc)*CIN*9 + (cb + c)*9;
        float* dst = w_s + c*384 + oc*8;
        #pragma unroll
        for (int dy = 0; dy < 3; dy++)
            #pragma unroll
            for (int dx = 0; dx < 3; dx++) {
                float w = src[dy*3 + dx];
                dst[dy*128 + dx*2]     = w;
                dst[dy*128 + dx*2 + 1] = w;
            }
    }
    __syncthreads();

    // ---- phase B: interior input fill (9 in-bounds rows, full 16 cols) ----
    {
        int c = tid >> 4, t16 = tid & 15;
        int gy0 = (y0 == 0) ? 0 : 7;          // first loaded global row
        int rr0 = gy0 - y0 + 1;               // its smem row
        const float* src = in + ((b*CIN + cb + c)*16 + gy0)*16;
        float* dstc = in_s + c*IN_PITCH;
        #pragma unroll
        for (int k = 0; k < 3; k++) {
            int v = t16 + k*16;
            if (v < 36) {                     // 9 rows * 4 quads
                int r = v >> 2, q = v & 3;
                float4 d = *(const float4*)(src + r*16 + q*4);
                int rr = rr0 + r;
                float* dp = dstc + rr*20 + 6*(rr & 1) + 1 + q*4;
                dp[0] = d.x; dp[1] = d.y; dp[2] = d.z; dp[3] = d.w;
            }
        }
    }
    __syncthreads();

    // ---- compute ----
    uint64_t acc[2][2];
    acc[0][0] = acc[0][1] = acc[1][0] = acc[1][1] = pk2(0.f, 0.f);

    const int off0 = (yl    )*20 + 6*((yl    ) & 1) + xb;
    const int off1 = (yl + 1)*20 + 6*((yl + 1) & 1) + xb;
    const int off2 = (yl + 2)*20 + 6*((yl + 2) & 1) + xb;

    const float* cin = in_s;
    const float* wc  = w_s + wid*16;
    #pragma unroll 1
    for (int c = 0; c < 16; c++) {
        #pragma unroll
        for (int dy = 0; dy < 3; dy++) {
            const int off = (dy == 0) ? off0 : (dy == 1) ? off1 : off2;
            const uint64_t* rp = (const uint64_t*)(cin + off);
            uint64_t E0 = rp[0], E1 = rp[1], E2 = rp[2];
            float a0,a1,a2,a3,a4,a5;
            upk(E0,a0,a1); upk(E1,a2,a3); upk(E2,a4,a5);
            uint64_t D0 = pk2(a1,a2), D1 = pk2(a3,a4);
            const float* wd = wc + dy*128;
            ulonglong2 wwA = *(const ulonglong2*)(wd);       // oc even: (w0,w0),(w1,w1)
            uint64_t   WA2 = *(const uint64_t*)(wd + 4);     // (w2,w2)
            ulonglong2 wwB = *(const ulonglong2*)(wd + 8);   // oc odd
            uint64_t   WB2 = *(const uint64_t*)(wd + 12);
            fma2(acc[0][0], E0, wwA.x); fma2(acc[0][0], D0, wwA.y); fma2(acc[0][0], E1, WA2);
            fma2(acc[0][1], E1, wwA.x); fma2(acc[0][1], D1, wwA.y); fma2(acc[0][1], E2, WA2);
            fma2(acc[1][0], E0, wwB.x); fma2(acc[1][0], D0, wwB.y); fma2(acc[1][0], E1, WB2);
            fma2(acc[1][1], E1, wwB.x); fma2(acc[1][1], D1, wwB.y); fma2(acc[1][1], E2, WB2);
        }
        cin += IN_PITCH;
        wc  += 384;
    }
    #pragma unroll
    for (int q = 0; q < 2; q++) {
        int oc = oc0 + wid*2 + q;
        float4 r;
        upk(acc[q][0], r.x, r.y);
        upk(acc[q][1], r.z, r.w);
        *(float4*)&slab[((b*128 + oc)*16 + (y0 + yl))*16 + xb] = r;
    }
}

// ---------------- conv1 tile (3 in-ch, 32x32), 4 units of 256 ----------------
__device__ __forceinline__ void conv1_tile(
    const float* __restrict__ s, const float* __restrict__ W1,
    float* __restrict__ slab, int tile, float* sm)
{
    int tid = threadIdx.x;
    for (int idx = tid; idx < 1728; idx += 256) sm[idx] = W1[idx];
    __syncthreads();
    #pragma unroll 1
    for (int u4 = 0; u4 < 4; u4++) {
        int u   = (tile*4 + u4)*256 + tid;
        int row = u >> 2;
        int xb  = (u & 3) * 8;
        int b   = row >> 11;
        int oc  = (row >> 5) & 63;
        int y   = row & 31;
        float acc[8];
        #pragma unroll
        for (int i = 0; i < 8; i++) acc[i] = 0.f;
        #pragma unroll
        for (int c = 0; c < 3; c++) {
            #pragma unroll
            for (int dy = 0; dy < 3; dy++) {
                int gy = y + dy - 1;
                if ((unsigned)gy >= 32u) continue;
                const float* srow = s + ((b*3 + c)*32 + gy)*32;
                float iv[10];
                #pragma unroll
                for (int t = 0; t < 10; t++) {
                    int gx = xb + t - 1;
                    iv[t] = ((unsigned)gx < 32u) ? srow[gx] : 0.f;
                }
                float w[3];
                #pragma unroll
                for (int dx = 0; dx < 3; dx++) w[dx] = sm[oc*27 + c*9 + dy*3 + dx];
                #pragma unroll
                for (int i = 0; i < 8; i++)
                    #pragma unroll
                    for (int dx = 0; dx < 3; dx++)
                        acc[i] += iv[i + dx] * w[dx];
            }
        }
        int base = ((b*64 + oc)*32 + y)*32 + xb;
        #pragma unroll
        for (int i = 0; i < 8; i++) slab[base + i] = acc[i];
    }
}

// ---------------- FC tile: out[b,j] = A[b,k0:k0+256] . W[j,k0:k0+256] ----------------
__device__ __forceinline__ void fc_tile(
    const float* __restrict__ A, const float* __restrict__ W,
    float* __restrict__ out, int K, int j0, int k0, float* sm)
{
    float* fs = sm;          // [16][64]
    float* ws = sm + 1024;   // [64][65]
    int tid = threadIdx.x;
    int tj  = tid & 31;
    int tb  = tid >> 5;
    float acc[2][2] = {{0.f,0.f},{0.f,0.f}};
    #pragma unroll 1
    for (int kc = k0; kc < k0 + 256; kc += 64) {
        __syncthreads();
        for (int idx = tid; idx < 1024; idx += 256) {
            int bb = idx >> 6, kk = idx & 63;
            fs[idx] = A[bb*K + kc + kk];
        }
        for (int idx = tid; idx < 4096; idx += 256) {
            int jl = idx >> 6, kk = idx & 63;
            ws[jl*65 + kk] = W[(j0 + jl)*K + kc + kk];
        }
        __syncthreads();
        #pragma unroll 4
        for (int kk = 0; kk < 64; kk++) {
            float w0 = ws[(tj*2    )*65 + kk];
            float w1 = ws[(tj*2 + 1)*65 + kk];
            float f0 = fs[ tb      *64 + kk];
            float f1 = fs[(tb + 8) *64 + kk];
            acc[0][0] += w0*f0;  acc[0][1] += w0*f1;
            acc[1][0] += w1*f0;  acc[1][1] += w1*f1;
        }
    }
    #pragma unroll
    for (int q = 0; q < 2; q++)
        #pragma unroll
        for (int r = 0; r < 2; r++)
            out[(tb + r*8)*1024 + (j0 + tj*2 + q)] = acc[q][r];
}

// ---------------- fc3: mo += o5 @ L3^T (single tile, deterministic) ----------------
__device__ __forceinline__ void fc3_part(
    const float* __restrict__ o5, const float* __restrict__ L3, float* __restrict__ mo)
{
    int t = threadIdx.x;
    if (t >= 160) return;
    int b = t / 10, j = t - b*10;
    const float* a = o5 + b*1024;
    const float* w = L3 + j*1024;
    float acc = 0.f;
    #pragma unroll 4
    for (int k = 0; k < 1024; k++) acc += a[k]*w[k];
    mo[t] += acc;
}

// ---------------- fat per-step kernel: work queue over 3777 uniform tiles ----------------
__global__ void __launch_bounds__(256, 4) conv_step(
    const float* __restrict__ W1, const float* __restrict__ W2,
    const float* __restrict__ W3, const float* __restrict__ L1,
    const float* __restrict__ L2, const float* __restrict__ L3)
{
    __shared__ __align__(16) float sm[9472];
    __shared__ int s_tile;
    for (;;) {
        __syncthreads();
        if (threadIdx.x == 0) s_tile = atomicAdd(&g_tick, 1);
        __syncthreads();
        int t = s_tile;
        if (t >= NT) return;
        if (t == 0) {
            fc3_part(g_o5, L3, g_mo);
        } else if (t < 2049) {               // conv3: 16b x 8ocg x 2yb x 8ks
            int i = t - 1;
            int ks = i & 7, yb = (i >> 3) & 1, ocg = (i >> 4) & 7, b = i >> 7;
            conv_tile(g_o2, W3, &g_s3[ks][0], 128, ks*16, b, ocg*16, yb*8, sm);
        } else if (t < 3073) {               // conv2: 16b x 8ocg x 2yb x 4ks
            int i = t - 2049;
            int ks = i & 3, yb = (i >> 2) & 1, ocg = (i >> 3) & 7, b = i >> 6;
            conv_tile(g_o1p, W2, &g_s2[ks][0], 64, ks*16, b, ocg*16, yb*8, sm);
        } else if (t < 3585) {               // fc1: 16jg x 32ks
            int i = t - 3073;
            int jg = i & 15, ks = i >> 4;
            fc_tile(g_f, L1, &g_s4[ks][0], 8192, jg*64, ks*256, sm);
        } else if (t < 3713) {               // conv1: 128 tiles x 4 units
            conv1_tile(g_s, W1, g_c1s, t - 3585, sm);
        } else {                             // fc2: 16jg x 4ks
            int i = t - 3713;
            int jg = i & 15, ks = i >> 4;
            fc_tile(g_o4, L2, &g_s5[ks][0], 1024, jg*64, ks*256, sm);
        }
    }
}

__global__ void write_out(float* __restrict__ out) {
    int t = threadIdx.x;
    if (t < 160) out[t] = g_mo[t];
}

extern "C" void kernel_launch(void* const* d_in, const int* in_sizes, int n_in,
                              void* d_out, int out_size)
{
    const float* x  = (const float*)d_in[0];
    const float* W1 = (const float*)d_in[1];
    const float* W2 = (const float*)d_in[2];
    const float* W3 = (const float*)d_in[3];
    const float* L1 = (const float*)d_in[4];
    const float* L2 = (const float*)d_in[5];
    const float* L3 = (const float*)d_in[6];

    zero_state<<<512, 256>>>();
    nop_k<<<1, 32>>>();
    for (int t = 0; t < T_STEPS; t++) {
        spike_step<<<3904, 256>>>(x);
        conv_step<<<GRID_CONV, 256>>>(W1, W2, W3, L1, L2, L3);
    }
    write_out<<<1, 192>>>((float*)d_out);
}